// round 10
// baseline (speedup 1.0000x reference)
#include <cuda_runtime.h>
#include <cstdint>

// QuaternionPositionToMatrixLayer: [N,7] f32 -> [N,3,4] f32 pose. Bandwidth-bound.
// Persistent blocks, grid-stride over 256-row tiles. Input: coalesced float4 LDG into
// smem. Output: staged to a DOUBLE-BUFFERED smem ring drained by 1D cp.async.bulk
// (TMA S2G); the drain of tile i overlaps load+compute of tile i+1, so the only
// exposed TMA wait is one per block instead of one per tile.

constexpr int TPB = 256;   // rows per tile == threads per block

__global__ __launch_bounds__(TPB) void quat_pose_kernel(
    const float4* __restrict__ in4,   // flat view of x, N*7 floats
    float4* __restrict__ out4,        // flat view of out, N*12 floats
    int n_rows, int n_tiles)
{
    __shared__ float  s_in[TPB * 7];                          // 7168 B
    __shared__ __align__(16) float4 s_out[2][TPB * 3];        // 2 x 12288 B

    const int t = threadIdx.x;
    int buf = 0;

    for (int tile = blockIdx.x; tile < n_tiles; tile += gridDim.x) {
        const long long row0 = (long long)tile * TPB;
        const int rows_here = min(TPB, n_rows - (int)row0);

        // ---- coalesced staged input ----
        {
            const long long base4 = row0 * 7 / 4;             // exact: row0 % 4 == 0
            const int nf4 = rows_here * 7 / 4;                // 448 for full tiles
            const int tail_floats = rows_here * 7 - nf4 * 4;  // 0 for full tiles
            float4* s4 = reinterpret_cast<float4*>(s_in);
            #pragma unroll
            for (int i = 0; i < 2; ++i) {
                int idx = t + i * TPB;
                if (idx < nf4) s4[idx] = __ldcs(&in4[base4 + idx]);
            }
            if (tail_floats) {   // not hit for N=4,000,000
                const float* inf = reinterpret_cast<const float*>(in4);
                for (int k = t; k < tail_floats; k += TPB)
                    s_in[nf4 * 4 + k] = inf[row0 * 7 + nf4 * 4 + k];
            }
        }

        // Ensure s_out[buf]'s previous TMA drain (committed 2 tiles ago) finished:
        // keep at most 1 bulk group in flight before we overwrite this buffer.
        if (t == 0)
            asm volatile("cp.async.bulk.wait_group.read 1;" ::: "memory");

        // One barrier covers: s_in ready for all, s_out[buf] free for all.
        __syncthreads();

        // ---- per-row compute (stride-7 smem reads: bank-conflict free) ----
        if (t < rows_here) {
            const float* r = s_in + t * 7;
            const float q0 = r[0], q1 = r[1], q2 = r[2], q3 = r[3];
            const float tx = r[4], ty = r[5], tz = r[6];

            const float q0q0 = q0 * q0, q1q1 = q1 * q1, q2q2 = q2 * q2, q3q3 = q3 * q3;
            const float q0q1 = q0 * q1, q0q2 = q0 * q2, q0q3 = q0 * q3;
            const float q1q2 = q1 * q2, q1q3 = q1 * q3, q2q3 = q2 * q3;

            float4 o0, o1, o2;
            o0.x = q0q0 + q1q1 - q2q2 - q3q3;     // r00
            o0.y = 2.0f * (q1q2 - q0q3);          // r01
            o0.z = 2.0f * (q1q3 + q0q2);          // r02
            o0.w = tx;
            o1.x = 2.0f * (q1q2 + q0q3);          // r10
            o1.y = q0q0 - q1q1 + q2q2 - q3q3;     // r11
            o1.z = 2.0f * (q2q3 - q0q1);          // r12
            o1.w = ty;
            o2.x = 2.0f * (q1q3 - q0q2);          // r20
            o2.y = 2.0f * (q2q3 + q0q1);          // r21
            o2.z = q0q0 - q1q1 - q2q2 + q3q3;     // r22
            o2.w = tz;

            // STS.128 at float4-stride 3 (word stride 12): conflict-free.
            s_out[buf][t * 3 + 0] = o0;
            s_out[buf][t * 3 + 1] = o1;
            s_out[buf][t * 3 + 2] = o2;
        }
        __syncthreads();   // all STS done (and all s_in reads done) before drain/reload

        // ---- async drain: 1D TMA bulk store of this tile's contiguous span ----
        if (t == 0 && rows_here > 0) {
            asm volatile("fence.proxy.async.shared::cta;" ::: "memory");
            unsigned int s_addr;
            asm("{ .reg .u64 a; cvta.to.shared.u64 a, %1; cvt.u32.u64 %0, a; }"
                : "=r"(s_addr) : "l"(&s_out[buf][0]));
            void* gptr = (void*)(out4 + row0 * 3);
            const unsigned int bytes = (unsigned int)(rows_here * 48);
            asm volatile(
                "cp.async.bulk.global.shared::cta.bulk_group [%0], [%1], %2;"
                :: "l"(gptr), "r"(s_addr), "r"(bytes) : "memory");
            asm volatile("cp.async.bulk.commit_group;" ::: "memory");
        }
        buf ^= 1;
    }

    // Smem must stay live until the TMA engine has read it.
    if (t == 0)
        asm volatile("cp.async.bulk.wait_group.read 0;" ::: "memory");
}

extern "C" void kernel_launch(void* const* d_in, const int* in_sizes, int n_in,
                              void* d_out, int out_size)
{
    const float4* in4 = (const float4*)d_in[0];
    float4* out4 = (float4*)d_out;
    const int n_rows = in_sizes[0] / 7;
    const int n_tiles = (n_rows + TPB - 1) / TPB;     // 15625 for N=4M
    int grid = 148 * 8;                               // persistent-ish: ~13 tiles/block
    if (grid > n_tiles) grid = n_tiles;
    quat_pose_kernel<<<grid, TPB>>>(in4, out4, n_rows, n_tiles);
}

// round 12
// speedup vs baseline: 1.1911x; 1.1911x over previous
#include <cuda_runtime.h>
#include <cstdint>

// QuaternionPositionToMatrixLayer: [N,7] f32 -> [N,3,4] f32 pose. Bandwidth-bound.
// Non-persistent (one 256-row tile per CTA; CTA oversubscription provides all the
// latency hiding). BOTH global streams ride the TMA engine:
//   input : 1D cp.async.bulk G2S (7168B contiguous span) + mbarrier complete_tx
//   output: 1D cp.async.bulk S2G (12288B contiguous span) + bulk_group wait
// Per-thread LSU work is only smem: stride-7 LDS reads + conflict-free STS.128.

constexpr int TPB = 256;   // rows per block == threads per block

__global__ __launch_bounds__(TPB) void quat_pose_kernel(
    const float4* __restrict__ in4,   // flat view of x, N*7 floats
    float4* __restrict__ out4,        // flat view of out, N*12 floats
    int n_rows)
{
    __shared__ __align__(16) float  s_in[TPB * 7];         // 7168 B
    __shared__ __align__(16) float4 s_out[TPB * 3];        // 12288 B
    __shared__ __align__(8)  unsigned long long mbar;

    const int t = threadIdx.x;
    const long long row0 = (long long)blockIdx.x * TPB;
    const int rows_here = min(TPB, n_rows - (int)row0);
    const bool full_tile = (rows_here == TPB);

    unsigned int mbar_addr, sin_addr;
    asm("{ .reg .u64 a; cvta.to.shared.u64 a, %1; cvt.u32.u64 %0, a; }"
        : "=r"(mbar_addr) : "l"(&mbar));
    asm("{ .reg .u64 a; cvta.to.shared.u64 a, %1; cvt.u32.u64 %0, a; }"
        : "=r"(sin_addr) : "l"(s_in));

    if (full_tile) {
        // ---- TMA bulk G2S input: one contiguous 7168B span ----
        if (t == 0) {
            asm volatile("mbarrier.init.shared.b64 [%0], %1;"
                         :: "r"(mbar_addr), "r"(1) : "memory");
        }
        __syncthreads();   // mbarrier visible to all before anyone waits on it
        if (t == 0) {
            const unsigned int bytes = TPB * 28;           // 7168
            asm volatile("mbarrier.arrive.expect_tx.shared.b64 _, [%0], %1;"
                         :: "r"(mbar_addr), "r"(bytes) : "memory");
            const void* gsrc = (const void*)((const char*)in4 + row0 * 28);
            asm volatile(
                "cp.async.bulk.shared::cluster.global.mbarrier::complete_tx::bytes "
                "[%0], [%1], %2, [%3];"
                :: "r"(sin_addr), "l"(gsrc), "r"(bytes), "r"(mbar_addr) : "memory");
        }
        // All threads wait for the TMA data (phase parity 0).
        {
            unsigned int done;
            asm volatile(
                "{\n\t.reg .pred p;\n\t"
                "mbarrier.try_wait.parity.acquire.cta.shared::cta.b64 p, [%1], %2;\n\t"
                "selp.b32 %0, 1, 0, p;\n\t}"
                : "=r"(done) : "r"(mbar_addr), "r"(0u) : "memory");
            if (!done) {
                asm volatile(
                    "{\n\t.reg .pred P1;\n\t"
                    "WL_%=:\n\t"
                    "mbarrier.try_wait.parity.acquire.cta.shared::cta.b64 P1, [%0], %1, 0x989680;\n\t"
                    "@P1 bra.uni WD_%=;\n\t"
                    "bra.uni WL_%=;\n\t"
                    "WD_%=:\n\t}"
                    :: "r"(mbar_addr), "r"(0u) : "memory");
            }
        }
    } else {
        // ---- generic tail path (not hit for N=4,000,000) ----
        const float* inf = reinterpret_cast<const float*>(in4);
        for (int k = t; k < rows_here * 7; k += TPB)
            s_in[k] = inf[row0 * 7 + k];
        __syncthreads();
    }

    // ---- per-row compute (stride-7 smem reads: bank-conflict free) ----
    if (t < rows_here) {
        const float* r = s_in + t * 7;
        const float q0 = r[0], q1 = r[1], q2 = r[2], q3 = r[3];
        const float tx = r[4], ty = r[5], tz = r[6];

        const float q0q0 = q0 * q0, q1q1 = q1 * q1, q2q2 = q2 * q2, q3q3 = q3 * q3;
        const float q0q1 = q0 * q1, q0q2 = q0 * q2, q0q3 = q0 * q3;
        const float q1q2 = q1 * q2, q1q3 = q1 * q3, q2q3 = q2 * q3;

        float4 o0, o1, o2;
        o0.x = q0q0 + q1q1 - q2q2 - q3q3;     // r00
        o0.y = 2.0f * (q1q2 - q0q3);          // r01
        o0.z = 2.0f * (q1q3 + q0q2);          // r02
        o0.w = tx;
        o1.x = 2.0f * (q1q2 + q0q3);          // r10
        o1.y = q0q0 - q1q1 + q2q2 - q3q3;     // r11
        o1.z = 2.0f * (q2q3 - q0q1);          // r12
        o1.w = ty;
        o2.x = 2.0f * (q1q3 - q0q2);          // r20
        o2.y = 2.0f * (q2q3 + q0q1);          // r21
        o2.z = q0q0 - q1q1 - q2q2 + q3q3;     // r22
        o2.w = tz;

        // STS.128 at float4-stride 3 (word stride 12): conflict-free per 8-lane phase.
        s_out[t * 3 + 0] = o0;
        s_out[t * 3 + 1] = o1;
        s_out[t * 3 + 2] = o2;
    }
    __syncthreads();

    // ---- output drain: single 1D TMA bulk store of the contiguous span ----
    if (t == 0 && rows_here > 0) {
        asm volatile("fence.proxy.async.shared::cta;" ::: "memory");
        unsigned int sout_addr;
        asm("{ .reg .u64 a; cvta.to.shared.u64 a, %1; cvt.u32.u64 %0, a; }"
            : "=r"(sout_addr) : "l"(s_out));
        void* gptr = (void*)(out4 + row0 * 3);
        const unsigned int bytes = (unsigned int)(rows_here * 48);  // multiple of 16
        asm volatile(
            "cp.async.bulk.global.shared::cta.bulk_group [%0], [%1], %2;"
            :: "l"(gptr), "r"(sout_addr), "r"(bytes) : "memory");
        asm volatile("cp.async.bulk.commit_group;" ::: "memory");
        // Smem must stay live until the TMA engine has read it.
        asm volatile("cp.async.bulk.wait_group.read 0;" ::: "memory");
    }
}

extern "C" void kernel_launch(void* const* d_in, const int* in_sizes, int n_in,
                              void* d_out, int out_size)
{
    const float4* in4 = (const float4*)d_in[0];
    float4* out4 = (float4*)d_out;
    const int n_rows = in_sizes[0] / 7;
    const int grid = (n_rows + TPB - 1) / TPB;   // 15625 for N=4M
    quat_pose_kernel<<<grid, TPB>>>(in4, out4, n_rows);
}

// round 13
// speedup vs baseline: 1.1981x; 1.0058x over previous
#include <cuda_runtime.h>
#include <cstdint>

// QuaternionPositionToMatrixLayer: [N,7] f32 -> [N,3,4] f32 pose. Bandwidth-bound.
// Non-persistent, one 512-row tile per CTA (TPB=512) — halves per-CTA fixed costs
// vs the 256-row version while keeping 2048 threads/SM. Both global streams ride
// the TMA engine:
//   input : 1D cp.async.bulk G2S (14336B contiguous span) + mbarrier complete_tx
//   output: 1D cp.async.bulk S2G (24576B contiguous span) + bulk_group wait
// Per-thread LSU work is only smem: stride-7 LDS reads + conflict-free STS.128.

constexpr int TPB = 512;   // rows per block == threads per block

__global__ __launch_bounds__(TPB) void quat_pose_kernel(
    const float4* __restrict__ in4,   // flat view of x, N*7 floats
    float4* __restrict__ out4,        // flat view of out, N*12 floats
    int n_rows)
{
    __shared__ __align__(16) float  s_in[TPB * 7];         // 14336 B
    __shared__ __align__(16) float4 s_out[TPB * 3];        // 24576 B
    __shared__ __align__(8)  unsigned long long mbar;

    const int t = threadIdx.x;
    const long long row0 = (long long)blockIdx.x * TPB;
    const int rows_here = min(TPB, n_rows - (int)row0);
    const bool full_tile = (rows_here == TPB);

    unsigned int mbar_addr, sin_addr;
    asm("{ .reg .u64 a; cvta.to.shared.u64 a, %1; cvt.u32.u64 %0, a; }"
        : "=r"(mbar_addr) : "l"(&mbar));
    asm("{ .reg .u64 a; cvta.to.shared.u64 a, %1; cvt.u32.u64 %0, a; }"
        : "=r"(sin_addr) : "l"(s_in));

    if (full_tile) {
        // ---- TMA bulk G2S input: one contiguous 14336B span ----
        if (t == 0) {
            asm volatile("mbarrier.init.shared.b64 [%0], %1;"
                         :: "r"(mbar_addr), "r"(1) : "memory");
        }
        __syncthreads();   // mbarrier visible before anyone waits on it
        if (t == 0) {
            const unsigned int bytes = TPB * 28;           // 14336
            asm volatile("mbarrier.arrive.expect_tx.shared.b64 _, [%0], %1;"
                         :: "r"(mbar_addr), "r"(bytes) : "memory");
            const void* gsrc = (const void*)((const char*)in4 + row0 * 28);
            asm volatile(
                "cp.async.bulk.shared::cluster.global.mbarrier::complete_tx::bytes "
                "[%0], [%1], %2, [%3];"
                :: "r"(sin_addr), "l"(gsrc), "r"(bytes), "r"(mbar_addr) : "memory");
        }
        // All threads wait for the TMA data (phase parity 0).
        {
            unsigned int done;
            asm volatile(
                "{\n\t.reg .pred p;\n\t"
                "mbarrier.try_wait.parity.acquire.cta.shared::cta.b64 p, [%1], %2;\n\t"
                "selp.b32 %0, 1, 0, p;\n\t}"
                : "=r"(done) : "r"(mbar_addr), "r"(0u) : "memory");
            if (!done) {
                asm volatile(
                    "{\n\t.reg .pred P1;\n\t"
                    "WL_%=:\n\t"
                    "mbarrier.try_wait.parity.acquire.cta.shared::cta.b64 P1, [%0], %1, 0x989680;\n\t"
                    "@P1 bra.uni WD_%=;\n\t"
                    "bra.uni WL_%=;\n\t"
                    "WD_%=:\n\t}"
                    :: "r"(mbar_addr), "r"(0u) : "memory");
            }
        }
    } else {
        // ---- generic tail path (hit once: last tile has 256 rows) ----
        const float* inf = reinterpret_cast<const float*>(in4);
        for (int k = t; k < rows_here * 7; k += TPB)
            s_in[k] = inf[row0 * 7 + k];
        __syncthreads();
    }

    // ---- per-row compute (stride-7 smem reads: bank-conflict free) ----
    if (t < rows_here) {
        const float* r = s_in + t * 7;
        const float q0 = r[0], q1 = r[1], q2 = r[2], q3 = r[3];
        const float tx = r[4], ty = r[5], tz = r[6];

        const float q0q0 = q0 * q0, q1q1 = q1 * q1, q2q2 = q2 * q2, q3q3 = q3 * q3;
        const float q0q1 = q0 * q1, q0q2 = q0 * q2, q0q3 = q0 * q3;
        const float q1q2 = q1 * q2, q1q3 = q1 * q3, q2q3 = q2 * q3;

        float4 o0, o1, o2;
        o0.x = q0q0 + q1q1 - q2q2 - q3q3;     // r00
        o0.y = 2.0f * (q1q2 - q0q3);          // r01
        o0.z = 2.0f * (q1q3 + q0q2);          // r02
        o0.w = tx;
        o1.x = 2.0f * (q1q2 + q0q3);          // r10
        o1.y = q0q0 - q1q1 + q2q2 - q3q3;     // r11
        o1.z = 2.0f * (q2q3 - q0q1);          // r12
        o1.w = ty;
        o2.x = 2.0f * (q1q3 - q0q2);          // r20
        o2.y = 2.0f * (q2q3 + q0q1);          // r21
        o2.z = q0q0 - q1q1 - q2q2 + q3q3;     // r22
        o2.w = tz;

        // STS.128 at float4-stride 3 (word stride 12): conflict-free per 8-lane phase.
        s_out[t * 3 + 0] = o0;
        s_out[t * 3 + 1] = o1;
        s_out[t * 3 + 2] = o2;
    }
    __syncthreads();

    // ---- output drain: single 1D TMA bulk store of the contiguous span ----
    if (t == 0 && rows_here > 0) {
        asm volatile("fence.proxy.async.shared::cta;" ::: "memory");
        unsigned int sout_addr;
        asm("{ .reg .u64 a; cvta.to.shared.u64 a, %1; cvt.u32.u64 %0, a; }"
            : "=r"(sout_addr) : "l"(s_out));
        void* gptr = (void*)(out4 + row0 * 3);
        const unsigned int bytes = (unsigned int)(rows_here * 48);  // multiple of 16
        asm volatile(
            "cp.async.bulk.global.shared::cta.bulk_group [%0], [%1], %2;"
            :: "l"(gptr), "r"(sout_addr), "r"(bytes) : "memory");
        asm volatile("cp.async.bulk.commit_group;" ::: "memory");
        // Smem must stay live until the TMA engine has read it.
        asm volatile("cp.async.bulk.wait_group.read 0;" ::: "memory");
    }
}

extern "C" void kernel_launch(void* const* d_in, const int* in_sizes, int n_in,
                              void* d_out, int out_size)
{
    const float4* in4 = (const float4*)d_in[0];
    float4* out4 = (float4*)d_out;
    const int n_rows = in_sizes[0] / 7;
    const int grid = (n_rows + TPB - 1) / TPB;   // 7813 for N=4M
    quat_pose_kernel<<<grid, TPB>>>(in4, out4, n_rows);
}